// round 1
// baseline (speedup 1.0000x reference)
#include <cuda_runtime.h>
#include <cuda_bf16.h>
#include <cstdint>

// Problem constants (fixed by the reference)
#define N_NODES 50000
#define N_EDGES 600000
#define D 128

// ---------------------------------------------------------------------------
// Scratch (device globals: allocation-free, graph-capturable)
// ---------------------------------------------------------------------------
__device__ float g_deg[N_NODES];
__device__ float g_norm[N_NODES];
__device__ float g_hs[N_NODES * D];   // prescaled features (h * norm)
__device__ float g_agg[N_NODES * D];  // scatter-add accumulator
__device__ float g_h1[N_NODES * D];   // layer-1 output (after relu)

// ---------------------------------------------------------------------------
// Degree / norm
// ---------------------------------------------------------------------------
__global__ void zero_deg_kernel() {
    int i = blockIdx.x * blockDim.x + threadIdx.x;
    if (i < N_NODES) g_deg[i] = 0.0f;
}

__global__ void deg_kernel(const int* __restrict__ dst) {
    int i = blockIdx.x * blockDim.x + threadIdx.x;
    if (i < N_EDGES) atomicAdd(&g_deg[dst[i]], 1.0f);
}

__global__ void norm_kernel() {
    int i = blockIdx.x * blockDim.x + threadIdx.x;
    if (i < N_NODES) g_norm[i] = rsqrtf(fmaxf(g_deg[i], 1.0f));
}

// ---------------------------------------------------------------------------
// Zero the aggregation buffer (float4 stores)
// ---------------------------------------------------------------------------
__global__ void zero_agg_kernel() {
    int i = blockIdx.x * blockDim.x + threadIdx.x;
    if (i < N_NODES * (D / 4)) {
        reinterpret_cast<float4*>(g_agg)[i] = make_float4(0.f, 0.f, 0.f, 0.f);
    }
}

// ---------------------------------------------------------------------------
// Prescale: hs[n, :] = h[n, :] * norm[n]   (float4 vectorized)
// ---------------------------------------------------------------------------
__global__ void prescale_kernel(const float4* __restrict__ h) {
    int i = blockIdx.x * blockDim.x + threadIdx.x;
    if (i < N_NODES * (D / 4)) {
        int node = i >> 5;  // D/4 = 32 chunks per node
        float nm = g_norm[node];
        float4 v = h[i];
        v.x *= nm; v.y *= nm; v.z *= nm; v.w *= nm;
        reinterpret_cast<float4*>(g_hs)[i] = v;
    }
}

// ---------------------------------------------------------------------------
// Edge scatter: agg[dst] += hs[src]  via red.global.add.v4.f32
// One thread per (edge, 4-float chunk): 32 threads per edge (one warp).
// ---------------------------------------------------------------------------
__global__ __launch_bounds__(256) void scatter_kernel(
    const int* __restrict__ src, const int* __restrict__ dst) {
    long long t = (long long)blockIdx.x * blockDim.x + threadIdx.x;
    int e = (int)(t >> 5);
    int c = (int)(t & 31);
    if (e >= N_EDGES) return;
    int s = __ldg(&src[e]);
    int d = __ldg(&dst[e]);
    float4 v = reinterpret_cast<const float4*>(g_hs)[s * 32 + c];
    float* ap = g_agg + (long long)d * D + c * 4;
    asm volatile("red.global.add.v4.f32 [%0], {%1, %2, %3, %4};"
                 :: "l"(ap), "f"(v.x), "f"(v.y), "f"(v.z), "f"(v.w)
                 : "memory");
}

// ---------------------------------------------------------------------------
// Epilogue: out[n, :] = relu?( (agg[n, :] * norm[n]) @ W + b )
// Block: 256 threads, tile = 64 rows x 128 cols.
//   smem: W full (128x128 fp32 = 64KB) + H tile (64x128 = 32KB) => 96KB dynamic
//   Thread (tx = tid&31, ty = tid>>5): 8 rows x 4 cols register tile.
//   Inner loop over k: broadcast LDS for A, LDS.128 for B row slice.
// ---------------------------------------------------------------------------
template <bool RELU>
__global__ __launch_bounds__(256) void epilogue_kernel(
    const float* __restrict__ agg, const float* __restrict__ W,
    const float* __restrict__ bias, float* __restrict__ out) {
    extern __shared__ float smem[];
    float* sW = smem;           // [128][128]
    float* sH = smem + D * D;   // [64][128]

    int tid = threadIdx.x;
    int row0 = blockIdx.x * 64;

    // Load W (coalesced)
    #pragma unroll 4
    for (int i = tid; i < D * D; i += 256) sW[i] = W[i];

    // Load 64 rows of agg, scaled by dst norm (coalesced, float4)
    for (int i = tid; i < 64 * (D / 4); i += 256) {
        int r = i >> 5;           // row in tile
        int c4 = i & 31;          // float4 chunk
        int node = row0 + r;
        float4 v = make_float4(0.f, 0.f, 0.f, 0.f);
        if (node < N_NODES) {
            float nm = g_norm[node];
            v = reinterpret_cast<const float4*>(agg)[node * 32 + c4];
            v.x *= nm; v.y *= nm; v.z *= nm; v.w *= nm;
        }
        reinterpret_cast<float4*>(sH)[i] = v;
    }
    __syncthreads();

    int tx = tid & 31;   // column group: cols [tx*4, tx*4+4)
    int ty = tid >> 5;   // row group:   rows [ty*8, ty*8+8)

    float acc[8][4];
    #pragma unroll
    for (int r = 0; r < 8; r++)
        #pragma unroll
        for (int j = 0; j < 4; j++) acc[r][j] = 0.f;

    #pragma unroll 4
    for (int k = 0; k < D; k++) {
        float4 b4 = reinterpret_cast<const float4*>(&sW[k * D])[tx];
        #pragma unroll
        for (int r = 0; r < 8; r++) {
            float a = sH[(ty * 8 + r) * D + k];  // warp-broadcast
            acc[r][0] += a * b4.x;
            acc[r][1] += a * b4.y;
            acc[r][2] += a * b4.z;
            acc[r][3] += a * b4.w;
        }
    }

    float4 bb = reinterpret_cast<const float4*>(bias)[tx];
    #pragma unroll
    for (int r = 0; r < 8; r++) {
        int node = row0 + ty * 8 + r;
        if (node < N_NODES) {
            float4 o;
            o.x = acc[r][0] + bb.x;
            o.y = acc[r][1] + bb.y;
            o.z = acc[r][2] + bb.z;
            o.w = acc[r][3] + bb.w;
            if (RELU) {
                o.x = fmaxf(o.x, 0.f); o.y = fmaxf(o.y, 0.f);
                o.z = fmaxf(o.z, 0.f); o.w = fmaxf(o.w, 0.f);
            }
            reinterpret_cast<float4*>(out)[node * 32 + tx] = o;
        }
    }
}

// ---------------------------------------------------------------------------
// Launch
// ---------------------------------------------------------------------------
extern "C" void kernel_launch(void* const* d_in, const int* in_sizes, int n_in,
                              void* d_out, int out_size) {
    const float* features = (const float*)d_in[0];
    const int*   src      = (const int*)d_in[1];
    const int*   dst      = (const int*)d_in[2];
    const float* W0       = (const float*)d_in[3];
    const float* b0       = (const float*)d_in[4];
    const float* W1       = (const float*)d_in[5];
    const float* b1       = (const float*)d_in[6];
    float* out = (float*)d_out;

    const int SMEM_EPI = (D * D + 64 * D) * sizeof(float);  // 96 KB
    cudaFuncSetAttribute(epilogue_kernel<true>,
                         cudaFuncAttributeMaxDynamicSharedMemorySize, SMEM_EPI);
    cudaFuncSetAttribute(epilogue_kernel<false>,
                         cudaFuncAttributeMaxDynamicSharedMemorySize, SMEM_EPI);

    const int nodesBlocks   = (N_NODES + 255) / 256;
    const int edgeBlocks    = (N_EDGES + 255) / 256;
    const int vecBlocks     = (N_NODES * (D / 4) + 255) / 256;   // 1.6M threads
    const long long scatterThreads = (long long)N_EDGES * 32;
    const int scatterBlocks = (int)((scatterThreads + 255) / 256);
    const int epiBlocks     = (N_NODES + 63) / 64;

    // Degree + norm
    zero_deg_kernel<<<nodesBlocks, 256>>>();
    deg_kernel<<<edgeBlocks, 256>>>(dst);
    norm_kernel<<<nodesBlocks, 256>>>();

    // Need g_agg / g_h1 symbol addresses for kernel args
    // (kernels reference globals directly; epilogue takes agg via param)
    // Layer 1
    prescale_kernel<<<vecBlocks, 256>>>((const float4*)features);
    zero_agg_kernel<<<vecBlocks, 256>>>();
    scatter_kernel<<<scatterBlocks, 256>>>(src, dst);
    {
        // epilogue reads g_agg via device-symbol pointer: pass through a
        // device-global alias. Simplest: get raw pointers with a tiny kernel-
        // free trick — use the globals directly via a launch lambda is not
        // possible, so pass via cudaGetSymbolAddress-free route: the kernels
        // can take the global directly. We pass nullptr-safe device pointers
        // obtained at first call (idempotent, capture-safe API).
        static float* agg_ptr = nullptr;
        static float* h1_ptr = nullptr;
        if (!agg_ptr) {
            cudaGetSymbolAddress((void**)&agg_ptr, g_agg);
            cudaGetSymbolAddress((void**)&h1_ptr, g_h1);
        }
        epilogue_kernel<true><<<epiBlocks, 256, SMEM_EPI>>>(agg_ptr, W0, b0, h1_ptr);

        // Layer 2
        prescale_kernel<<<vecBlocks, 256>>>((const float4*)h1_ptr);
        zero_agg_kernel<<<vecBlocks, 256>>>();
        scatter_kernel<<<scatterBlocks, 256>>>(src, dst);
        epilogue_kernel<false><<<epiBlocks, 256, SMEM_EPI>>>(agg_ptr, W1, b1, out);
    }
}

// round 2
// speedup vs baseline: 1.4069x; 1.4069x over previous
#include <cuda_runtime.h>
#include <cuda_bf16.h>
#include <cstdint>

#define N_NODES 50000
#define N_EDGES 600000
#define D 128

// ---------------------------------------------------------------------------
// Scratch (device globals: allocation-free, graph-capturable)
// ---------------------------------------------------------------------------
__device__ int   g_deg_i[N_NODES];
__device__ int   g_cursor[N_NODES];
__device__ int   g_off[N_NODES + 1];
__device__ int   g_esrc[N_EDGES];
__device__ float g_norm[N_NODES];
__device__ float g_agg[N_NODES * D];  // aggregated (dst-norm applied)
__device__ float g_h1[N_NODES * D];   // layer-1 output (after relu)

// ---------------------------------------------------------------------------
// CSR build: zero, histogram, scan, fill
// ---------------------------------------------------------------------------
__global__ void zero_kernel() {
    int i = blockIdx.x * blockDim.x + threadIdx.x;
    if (i < N_NODES) { g_deg_i[i] = 0; g_cursor[i] = 0; }
}

__global__ void hist_kernel(const int* __restrict__ dst) {
    int i = blockIdx.x * blockDim.x + threadIdx.x;
    if (i < N_EDGES) atomicAdd(&g_deg_i[dst[i]], 1);
}

__device__ __forceinline__ int warp_incl_scan(int x, int lane) {
    #pragma unroll
    for (int ofs = 1; ofs < 32; ofs <<= 1) {
        int t = __shfl_up_sync(0xFFFFFFFFu, x, ofs);
        if (lane >= ofs) x += t;
    }
    return x;
}

// Single-block exclusive scan of g_deg_i -> g_off (50k elements, 1024 threads)
__global__ __launch_bounds__(1024) void scan_kernel() {
    __shared__ int wsum[32];
    __shared__ int carry_s;
    int tid  = threadIdx.x;
    int lane = tid & 31;
    int wid  = tid >> 5;
    if (tid == 0) carry_s = 0;
    __syncthreads();

    for (int base = 0; base < N_NODES; base += 1024) {
        int idx = base + tid;
        int v = (idx < N_NODES) ? g_deg_i[idx] : 0;
        int incl = warp_incl_scan(v, lane);
        if (lane == 31) wsum[wid] = incl;
        __syncthreads();
        if (wid == 0) {
            int s  = wsum[lane];
            int si = warp_incl_scan(s, lane);
            wsum[lane] = si - s;  // exclusive warp offset
        }
        __syncthreads();
        int tile_incl = incl + wsum[wid];
        int c = carry_s;
        if (idx < N_NODES) g_off[idx] = c + tile_incl - v;
        __syncthreads();  // all reads of carry_s before update
        if (tid == 1023) carry_s = c + tile_incl;
        __syncthreads();
    }
    if (tid == 0) g_off[N_NODES] = carry_s;
}

__global__ void norm_kernel() {
    int i = blockIdx.x * blockDim.x + threadIdx.x;
    if (i < N_NODES) g_norm[i] = rsqrtf(fmaxf((float)g_deg_i[i], 1.0f));
}

__global__ void fill_kernel(const int* __restrict__ src,
                            const int* __restrict__ dst) {
    int e = blockIdx.x * blockDim.x + threadIdx.x;
    if (e < N_EDGES) {
        int d = dst[e];
        int pos = atomicAdd(&g_cursor[d], 1);
        g_esrc[g_off[d] + pos] = src[e];
    }
}

// ---------------------------------------------------------------------------
// CSR aggregate: one warp per dst node.
//   agg[n, :] = norm[n] * sum_{e in adj(n)} h[src_e, :] * norm[src_e]
// Lane owns one float4 chunk (32 chunks = 128 floats). Unroll-by-2 for MLP.
// ---------------------------------------------------------------------------
template <bool LAYER1>
__global__ __launch_bounds__(256) void aggregate_kernel(const float4* __restrict__ hin) {
    int warp = (blockIdx.x * blockDim.x + threadIdx.x) >> 5;
    int lane = threadIdx.x & 31;
    if (warp >= N_NODES) return;
    const float4* __restrict__ h =
        LAYER1 ? hin : reinterpret_cast<const float4*>(g_h1);

    int beg = g_off[warp];
    int end = g_off[warp + 1];

    float4 acc = make_float4(0.f, 0.f, 0.f, 0.f);
    int i = beg;
    for (; i + 2 <= end; i += 2) {
        int s0 = __ldg(&g_esrc[i]);
        int s1 = __ldg(&g_esrc[i + 1]);
        float n0 = g_norm[s0];
        float n1 = g_norm[s1];
        float4 v0 = h[s0 * 32 + lane];
        float4 v1 = h[s1 * 32 + lane];
        acc.x += v0.x * n0; acc.y += v0.y * n0;
        acc.z += v0.z * n0; acc.w += v0.w * n0;
        acc.x += v1.x * n1; acc.y += v1.y * n1;
        acc.z += v1.z * n1; acc.w += v1.w * n1;
    }
    if (i < end) {
        int s0 = __ldg(&g_esrc[i]);
        float n0 = g_norm[s0];
        float4 v0 = h[s0 * 32 + lane];
        acc.x += v0.x * n0; acc.y += v0.y * n0;
        acc.z += v0.z * n0; acc.w += v0.w * n0;
    }
    float dn = g_norm[warp];
    acc.x *= dn; acc.y *= dn; acc.z *= dn; acc.w *= dn;
    reinterpret_cast<float4*>(g_agg)[warp * 32 + lane] = acc;
}

// ---------------------------------------------------------------------------
// Epilogue GEMM: out[n, :] = relu?( agg[n, :] @ W + b )
// 64-row x 128-col tile per block; 8x4 register tile per thread.
// Inner product via packed fma.rn.f32x2 (2 FMAs per instruction).
// ---------------------------------------------------------------------------
template <bool LAYER1>
__global__ __launch_bounds__(256) void epilogue_kernel(
    const float* __restrict__ W, const float* __restrict__ bias,
    float* __restrict__ outp) {
    extern __shared__ float smem[];
    float* sW = smem;           // [128][128]
    float* sH = smem + D * D;   // [64][128]

    int tid  = threadIdx.x;
    int row0 = blockIdx.x * 64;

    #pragma unroll 4
    for (int i = tid; i < D * D; i += 256) sW[i] = W[i];

    for (int i = tid; i < 64 * (D / 4); i += 256) {
        int r  = i >> 5;
        int c4 = i & 31;
        int node = row0 + r;
        float4 v = make_float4(0.f, 0.f, 0.f, 0.f);
        if (node < N_NODES)
            v = reinterpret_cast<const float4*>(g_agg)[node * 32 + c4];
        reinterpret_cast<float4*>(sH)[i] = v;
    }
    __syncthreads();

    int tx = tid & 31;   // cols [tx*4, tx*4+4)
    int ty = tid >> 5;   // rows [ty*8, ty*8+8)

    unsigned long long acc[8][2];
    #pragma unroll
    for (int r = 0; r < 8; r++) { acc[r][0] = 0ull; acc[r][1] = 0ull; }

    #pragma unroll 4
    for (int k = 0; k < D; k++) {
        ulonglong2 b2 = reinterpret_cast<const ulonglong2*>(&sW[k * D])[tx];
        #pragma unroll
        for (int r = 0; r < 8; r++) {
            float a = sH[(ty * 8 + r) * D + k];  // warp-broadcast
            unsigned long long a2;
            asm("mov.b64 %0, {%1, %1};" : "=l"(a2) : "f"(a));
            asm("fma.rn.f32x2 %0, %1, %2, %0;" : "+l"(acc[r][0]) : "l"(a2), "l"(b2.x));
            asm("fma.rn.f32x2 %0, %1, %2, %0;" : "+l"(acc[r][1]) : "l"(a2), "l"(b2.y));
        }
    }

    float4 bb = reinterpret_cast<const float4*>(bias)[tx];
    #pragma unroll
    for (int r = 0; r < 8; r++) {
        int node = row0 + ty * 8 + r;
        if (node < N_NODES) {
            float4 o;
            asm("mov.b64 {%0, %1}, %2;" : "=f"(o.x), "=f"(o.y) : "l"(acc[r][0]));
            asm("mov.b64 {%0, %1}, %2;" : "=f"(o.z), "=f"(o.w) : "l"(acc[r][1]));
            o.x += bb.x; o.y += bb.y; o.z += bb.z; o.w += bb.w;
            if (LAYER1) {
                o.x = fmaxf(o.x, 0.f); o.y = fmaxf(o.y, 0.f);
                o.z = fmaxf(o.z, 0.f); o.w = fmaxf(o.w, 0.f);
            }
            float* dst = LAYER1 ? g_h1 : outp;
            reinterpret_cast<float4*>(dst)[node * 32 + tx] = o;
        }
    }
}

// ---------------------------------------------------------------------------
// Launch
// ---------------------------------------------------------------------------
extern "C" void kernel_launch(void* const* d_in, const int* in_sizes, int n_in,
                              void* d_out, int out_size) {
    const float* features = (const float*)d_in[0];
    const int*   src      = (const int*)d_in[1];
    const int*   dst      = (const int*)d_in[2];
    const float* W0       = (const float*)d_in[3];
    const float* b0       = (const float*)d_in[4];
    const float* W1       = (const float*)d_in[5];
    const float* b1       = (const float*)d_in[6];
    float* out = (float*)d_out;

    const int SMEM_EPI = (D * D + 64 * D) * sizeof(float);  // 96 KB
    cudaFuncSetAttribute(epilogue_kernel<true>,
                         cudaFuncAttributeMaxDynamicSharedMemorySize, SMEM_EPI);
    cudaFuncSetAttribute(epilogue_kernel<false>,
                         cudaFuncAttributeMaxDynamicSharedMemorySize, SMEM_EPI);

    const int nodesBlocks = (N_NODES + 255) / 256;
    const int edgeBlocks  = (N_EDGES + 255) / 256;
    const int aggBlocks   = (N_NODES + 7) / 8;     // 8 warps/block, warp/node
    const int epiBlocks   = (N_NODES + 63) / 64;

    // CSR build + norm
    zero_kernel<<<nodesBlocks, 256>>>();
    hist_kernel<<<edgeBlocks, 256>>>(dst);
    scan_kernel<<<1, 1024>>>();
    norm_kernel<<<nodesBlocks, 256>>>();
    fill_kernel<<<edgeBlocks, 256>>>(src, dst);

    // Layer 1
    aggregate_kernel<true><<<aggBlocks, 256>>>((const float4*)features);
    epilogue_kernel<true><<<epiBlocks, 256, SMEM_EPI>>>(W0, b0, nullptr);

    // Layer 2
    aggregate_kernel<false><<<aggBlocks, 256>>>(nullptr);
    epilogue_kernel<false><<<epiBlocks, 256, SMEM_EPI>>>(W1, b1, out);
}

// round 3
// speedup vs baseline: 1.4948x; 1.0625x over previous
#include <cuda_runtime.h>
#include <cuda_bf16.h>
#include <cstdint>

#define N_NODES 50000
#define N_EDGES 600000
#define D 128

// ---------------------------------------------------------------------------
// Scratch (device globals: allocation-free, graph-capturable)
// ---------------------------------------------------------------------------
__device__ int   g_deg_i[N_NODES];
__device__ int   g_cursor[N_NODES];
__device__ int   g_off[N_NODES + 1];
__device__ int   g_esrc[N_EDGES];
__device__ float g_norm[N_NODES];
__device__ float g_agg[N_NODES * D];  // aggregated (both norms applied)
__device__ float g_h1[N_NODES * D];   // layer-1 output (after relu)

// ---------------------------------------------------------------------------
// CSR build: zero, histogram, scan, fill(+norm)
// ---------------------------------------------------------------------------
__global__ void zero_kernel() {
    int i = blockIdx.x * blockDim.x + threadIdx.x;
    if (i < N_NODES) { g_deg_i[i] = 0; g_cursor[i] = 0; }
}

__global__ void hist_kernel(const int* __restrict__ dst) {
    int i = blockIdx.x * blockDim.x + threadIdx.x;
    if (i < N_EDGES) atomicAdd(&g_deg_i[dst[i]], 1);
}

__device__ __forceinline__ int warp_incl_scan(int x, int lane) {
    #pragma unroll
    for (int ofs = 1; ofs < 32; ofs <<= 1) {
        int t = __shfl_up_sync(0xFFFFFFFFu, x, ofs);
        if (lane >= ofs) x += t;
    }
    return x;
}

// Single-block exclusive scan of g_deg_i -> g_off (proven in round 1)
__global__ __launch_bounds__(1024) void scan_kernel() {
    __shared__ int wsum[32];
    __shared__ int carry_s;
    int tid  = threadIdx.x;
    int lane = tid & 31;
    int wid  = tid >> 5;
    if (tid == 0) carry_s = 0;
    __syncthreads();

    for (int base = 0; base < N_NODES; base += 1024) {
        int idx = base + tid;
        int v = (idx < N_NODES) ? g_deg_i[idx] : 0;
        int incl = warp_incl_scan(v, lane);
        if (lane == 31) wsum[wid] = incl;
        __syncthreads();
        if (wid == 0) {
            int s  = wsum[lane];
            int si = warp_incl_scan(s, lane);
            wsum[lane] = si - s;
        }
        __syncthreads();
        int tile_incl = incl + wsum[wid];
        int c = carry_s;
        if (idx < N_NODES) g_off[idx] = c + tile_incl - v;
        __syncthreads();
        if (tid == 1023) carry_s = c + tile_incl;
        __syncthreads();
    }
    if (tid == 0) g_off[N_NODES] = carry_s;
}

// fill edge lists + compute norm (fused; both depend only on deg/off)
__global__ void fill_norm_kernel(const int* __restrict__ src,
                                 const int* __restrict__ dst) {
    int e = blockIdx.x * blockDim.x + threadIdx.x;
    if (e < N_NODES)
        g_norm[e] = rsqrtf(fmaxf((float)g_deg_i[e], 1.0f));
    if (e < N_EDGES) {
        int d = dst[e];
        int pos = atomicAdd(&g_cursor[d], 1);
        g_esrc[g_off[d] + pos] = src[e];
    }
}

// ---------------------------------------------------------------------------
// CSR aggregate: one warp per dst node, unroll-4 for MLP.
//   agg[n, :] = norm[n] * sum_{e in adj(n)} h[src_e, :] * norm[src_e]
// ---------------------------------------------------------------------------
template <bool LAYER1>
__global__ __launch_bounds__(256) void aggregate_kernel(const float4* __restrict__ hin) {
    int warp = (blockIdx.x * blockDim.x + threadIdx.x) >> 5;
    int lane = threadIdx.x & 31;
    if (warp >= N_NODES) return;
    const float4* __restrict__ h =
        LAYER1 ? hin : reinterpret_cast<const float4*>(g_h1);

    int beg = g_off[warp];
    int end = g_off[warp + 1];

    float4 acc = make_float4(0.f, 0.f, 0.f, 0.f);
    int i = beg;
    for (; i + 4 <= end; i += 4) {
        int s0 = __ldg(&g_esrc[i]);
        int s1 = __ldg(&g_esrc[i + 1]);
        int s2 = __ldg(&g_esrc[i + 2]);
        int s3 = __ldg(&g_esrc[i + 3]);
        float n0 = g_norm[s0], n1 = g_norm[s1];
        float n2 = g_norm[s2], n3 = g_norm[s3];
        float4 v0 = h[s0 * 32 + lane];
        float4 v1 = h[s1 * 32 + lane];
        float4 v2 = h[s2 * 32 + lane];
        float4 v3 = h[s3 * 32 + lane];
        acc.x += v0.x * n0; acc.y += v0.y * n0; acc.z += v0.z * n0; acc.w += v0.w * n0;
        acc.x += v1.x * n1; acc.y += v1.y * n1; acc.z += v1.z * n1; acc.w += v1.w * n1;
        acc.x += v2.x * n2; acc.y += v2.y * n2; acc.z += v2.z * n2; acc.w += v2.w * n2;
        acc.x += v3.x * n3; acc.y += v3.y * n3; acc.z += v3.z * n3; acc.w += v3.w * n3;
    }
    for (; i < end; i++) {
        int s0 = __ldg(&g_esrc[i]);
        float n0 = g_norm[s0];
        float4 v0 = h[s0 * 32 + lane];
        acc.x += v0.x * n0; acc.y += v0.y * n0; acc.z += v0.z * n0; acc.w += v0.w * n0;
    }
    float dn = g_norm[warp];
    acc.x *= dn; acc.y *= dn; acc.z *= dn; acc.w *= dn;
    reinterpret_cast<float4*>(g_agg)[warp * 32 + lane] = acc;
}

// ---------------------------------------------------------------------------
// Epilogue GEMM: out[n, :] = relu?( agg[n, :] @ W + b )
// 128-row x 128-col tile per block, 512 threads, 8x4 register tile/thread.
// k-loop in steps of 4: vectorized LDS.128 for A, packed fma.rn.f32x2.
// smem: W (64KB) + H tile (64KB) = 128KB
// ---------------------------------------------------------------------------
template <bool LAYER1>
__global__ __launch_bounds__(512) void epilogue_kernel(
    const float* __restrict__ W, const float* __restrict__ bias,
    float* __restrict__ outp) {
    extern __shared__ float smem[];
    float* sW = smem;           // [128][128]
    float* sH = smem + D * D;   // [128][128]

    int tid  = threadIdx.x;
    int row0 = blockIdx.x * 128;

    #pragma unroll 4
    for (int i = tid; i < D * D / 4; i += 512)
        reinterpret_cast<float4*>(sW)[i] =
            reinterpret_cast<const float4*>(W)[i];

    for (int i = tid; i < 128 * (D / 4); i += 512) {
        int r  = i >> 5;
        int c4 = i & 31;
        int node = row0 + r;
        float4 v = make_float4(0.f, 0.f, 0.f, 0.f);
        if (node < N_NODES)
            v = reinterpret_cast<const float4*>(g_agg)[node * 32 + c4];
        reinterpret_cast<float4*>(sH)[i] = v;
    }
    __syncthreads();

    int tx = tid & 31;   // cols [tx*4, tx*4+4)
    int ty = tid >> 5;   // rows [ty*8, ty*8+8)  (ty in 0..15)

    unsigned long long acc[8][2];
    #pragma unroll
    for (int r = 0; r < 8; r++) { acc[r][0] = 0ull; acc[r][1] = 0ull; }

    for (int k = 0; k < D; k += 4) {
        // B slices for k..k+3 at this thread's 4 columns
        ulonglong2 b0 = reinterpret_cast<const ulonglong2*>(&sW[(k + 0) * D])[tx];
        ulonglong2 b1 = reinterpret_cast<const ulonglong2*>(&sW[(k + 1) * D])[tx];
        ulonglong2 b2 = reinterpret_cast<const ulonglong2*>(&sW[(k + 2) * D])[tx];
        ulonglong2 b3 = reinterpret_cast<const ulonglong2*>(&sW[(k + 3) * D])[tx];
        #pragma unroll
        for (int r = 0; r < 8; r++) {
            float4 a4 = *reinterpret_cast<const float4*>(
                &sH[(ty * 8 + r) * D + k]);  // broadcast LDS.128
            unsigned long long a2;
            asm("mov.b64 %0, {%1, %1};" : "=l"(a2) : "f"(a4.x));
            asm("fma.rn.f32x2 %0, %1, %2, %0;" : "+l"(acc[r][0]) : "l"(a2), "l"(b0.x));
            asm("fma.rn.f32x2 %0, %1, %2, %0;" : "+l"(acc[r][1]) : "l"(a2), "l"(b0.y));
            asm("mov.b64 %0, {%1, %1};" : "=l"(a2) : "f"(a4.y));
            asm("fma.rn.f32x2 %0, %1, %2, %0;" : "+l"(acc[r][0]) : "l"(a2), "l"(b1.x));
            asm("fma.rn.f32x2 %0, %1, %2, %0;" : "+l"(acc[r][1]) : "l"(a2), "l"(b1.y));
            asm("mov.b64 %0, {%1, %1};" : "=l"(a2) : "f"(a4.z));
            asm("fma.rn.f32x2 %0, %1, %2, %0;" : "+l"(acc[r][0]) : "l"(a2), "l"(b2.x));
            asm("fma.rn.f32x2 %0, %1, %2, %0;" : "+l"(acc[r][1]) : "l"(a2), "l"(b2.y));
            asm("mov.b64 %0, {%1, %1};" : "=l"(a2) : "f"(a4.w));
            asm("fma.rn.f32x2 %0, %1, %2, %0;" : "+l"(acc[r][0]) : "l"(a2), "l"(b3.x));
            asm("fma.rn.f32x2 %0, %1, %2, %0;" : "+l"(acc[r][1]) : "l"(a2), "l"(b3.y));
        }
    }

    float4 bb = reinterpret_cast<const float4*>(bias)[tx];
    #pragma unroll
    for (int r = 0; r < 8; r++) {
        int node = row0 + ty * 8 + r;
        if (node < N_NODES) {
            float4 o;
            asm("mov.b64 {%0, %1}, %2;" : "=f"(o.x), "=f"(o.y) : "l"(acc[r][0]));
            asm("mov.b64 {%0, %1}, %2;" : "=f"(o.z), "=f"(o.w) : "l"(acc[r][1]));
            o.x += bb.x; o.y += bb.y; o.z += bb.z; o.w += bb.w;
            if (LAYER1) {
                o.x = fmaxf(o.x, 0.f); o.y = fmaxf(o.y, 0.f);
                o.z = fmaxf(o.z, 0.f); o.w = fmaxf(o.w, 0.f);
            }
            float* dst = LAYER1 ? g_h1 : outp;
            reinterpret_cast<float4*>(dst)[node * 32 + tx] = o;
        }
    }
}

// ---------------------------------------------------------------------------
// Launch
// ---------------------------------------------------------------------------
extern "C" void kernel_launch(void* const* d_in, const int* in_sizes, int n_in,
                              void* d_out, int out_size) {
    const float* features = (const float*)d_in[0];
    const int*   src      = (const int*)d_in[1];
    const int*   dst      = (const int*)d_in[2];
    const float* W0       = (const float*)d_in[3];
    const float* b0       = (const float*)d_in[4];
    const float* W1       = (const float*)d_in[5];
    const float* b1       = (const float*)d_in[6];
    float* out = (float*)d_out;

    const int SMEM_EPI = (D * D + 128 * D) * sizeof(float);  // 128 KB
    cudaFuncSetAttribute(epilogue_kernel<true>,
                         cudaFuncAttributeMaxDynamicSharedMemorySize, SMEM_EPI);
    cudaFuncSetAttribute(epilogue_kernel<false>,
                         cudaFuncAttributeMaxDynamicSharedMemorySize, SMEM_EPI);

    const int nodesBlocks = (N_NODES + 255) / 256;
    const int edgeBlocks  = (N_EDGES + 255) / 256;
    const int aggBlocks   = (N_NODES + 7) / 8;      // 8 warps/block, warp/node
    const int epiBlocks   = (N_NODES + 127) / 128;

    // CSR build + norm
    zero_kernel<<<nodesBlocks, 256>>>();
    hist_kernel<<<edgeBlocks, 256>>>(dst);
    scan_kernel<<<1, 1024>>>();
    fill_norm_kernel<<<edgeBlocks, 256>>>(src, dst);

    // Layer 1
    aggregate_kernel<true><<<aggBlocks, 256>>>((const float4*)features);
    epilogue_kernel<true><<<epiBlocks, 512, SMEM_EPI>>>(W0, b0, nullptr);

    // Layer 2
    aggregate_kernel<false><<<aggBlocks, 256>>>(nullptr);
    epilogue_kernel<false><<<epiBlocks, 512, SMEM_EPI>>>(W1, b1, out);
}

// round 4
// speedup vs baseline: 1.5915x; 1.0647x over previous
#include <cuda_runtime.h>
#include <cuda_bf16.h>
#include <cstdint>

#define N_NODES 50000
#define N_EDGES 600000
#define D 128
#define SCAN_BLK 1024
#define NB ((N_NODES + SCAN_BLK - 1) / SCAN_BLK)   // 49

// ---------------------------------------------------------------------------
// Scratch (device globals: allocation-free, graph-capturable)
// ---------------------------------------------------------------------------
__device__ int   g_deg_i[N_NODES];
__device__ int   g_cursor[N_NODES];
__device__ int   g_off[N_NODES + 1];
__device__ int   g_bsum[NB + 1];
__device__ int   g_esrc[N_EDGES];
__device__ float g_enorm[N_EDGES];    // norm[src] per edge, CSR order
__device__ float g_norm[N_NODES];
__device__ float g_agg[N_NODES * D];
__device__ float g_h1[N_NODES * D];

// ---------------------------------------------------------------------------
// CSR build
// ---------------------------------------------------------------------------
__global__ void zero_kernel() {
    int i = blockIdx.x * blockDim.x + threadIdx.x;
    if (i < N_NODES) g_deg_i[i] = 0;
}

__global__ void hist_kernel(const int* __restrict__ dst) {
    int i = blockIdx.x * blockDim.x + threadIdx.x;
    if (i < N_EDGES) atomicAdd(&g_deg_i[dst[i]], 1);
}

__device__ __forceinline__ int warp_incl_scan(int x, int lane) {
    #pragma unroll
    for (int ofs = 1; ofs < 32; ofs <<= 1) {
        int t = __shfl_up_sync(0xFFFFFFFFu, x, ofs);
        if (lane >= ofs) x += t;
    }
    return x;
}

// Phase A: per-block inclusive scan of deg -> g_off (block-local), block sums.
__global__ __launch_bounds__(SCAN_BLK) void scanA_kernel() {
    __shared__ int wsum[32];
    int tid = threadIdx.x, lane = tid & 31, wid = tid >> 5;
    int idx = blockIdx.x * SCAN_BLK + tid;
    int v = (idx < N_NODES) ? g_deg_i[idx] : 0;
    int incl = warp_incl_scan(v, lane);
    if (lane == 31) wsum[wid] = incl;
    __syncthreads();
    if (wid == 0) {
        int s = wsum[lane];
        int si = warp_incl_scan(s, lane);
        wsum[lane] = si - s;
    }
    __syncthreads();
    int bincl = incl + wsum[wid];
    if (idx < N_NODES) g_off[idx] = bincl;       // block-local inclusive
    if (tid == SCAN_BLK - 1) g_bsum[blockIdx.x] = bincl;
}

// Phase B: exclusive scan of NB block sums (tiny, one block).
__global__ void scanB_kernel() {
    __shared__ int s[NB + 1];
    int tid = threadIdx.x;
    if (tid < NB) s[tid] = g_bsum[tid];
    __syncthreads();
    if (tid == 0) {
        int run = 0;
        for (int i = 0; i < NB; i++) { int t = s[i]; s[i] = run; run += t; }
        s[NB] = run;
    }
    __syncthreads();
    if (tid < NB) g_bsum[tid] = s[tid];
    if (tid == 0) g_off[N_NODES] = s[NB];
}

// Phase C: finalize exclusive offsets, init cursor (absolute) + norm.
__global__ __launch_bounds__(SCAN_BLK) void scanC_kernel() {
    int idx = blockIdx.x * SCAN_BLK + threadIdx.x;
    if (idx < N_NODES) {
        int d = g_deg_i[idx];
        int excl = g_bsum[blockIdx.x] + g_off[idx] - d;
        g_off[idx] = excl;
        g_cursor[idx] = excl;
        g_norm[idx] = rsqrtf(fmaxf((float)d, 1.0f));
    }
}

// Fill CSR edge lists: src index + norm[src] per slot (absolute cursor).
__global__ void fill_kernel(const int* __restrict__ src,
                            const int* __restrict__ dst) {
    int e = blockIdx.x * blockDim.x + threadIdx.x;
    if (e < N_EDGES) {
        int s = src[e];
        int pos = atomicAdd(&g_cursor[dst[e]], 1);
        g_esrc[pos]  = s;
        g_enorm[pos] = g_norm[s];
    }
}

// ---------------------------------------------------------------------------
// CSR aggregate: one warp per dst node.
// Lanes cooperatively load up to 32 (src, norm) pairs coalesced, broadcast via
// shfl -> row-gather addresses are register-resident, 4 independent LDG.128
// per unrolled step (no dependent-load chain).
// ---------------------------------------------------------------------------
template <bool LAYER1>
__global__ __launch_bounds__(256) void aggregate_kernel(const float4* __restrict__ hin) {
    int warp = (blockIdx.x * blockDim.x + threadIdx.x) >> 5;
    int lane = threadIdx.x & 31;
    if (warp >= N_NODES) return;
    const float4* __restrict__ h =
        LAYER1 ? hin : reinterpret_cast<const float4*>(g_h1);

    int beg = g_off[warp];
    int end = g_off[warp + 1];

    float4 acc = make_float4(0.f, 0.f, 0.f, 0.f);

    for (int base = beg; base < end; base += 32) {
        int n = end - base;
        if (n > 32) n = 32;
        int   si = 0;
        float ni = 0.f;
        if (lane < n) {
            si = __ldg(&g_esrc[base + lane]);    // coalesced
            ni = __ldg(&g_enorm[base + lane]);   // coalesced
        }
        int j = 0;
        for (; j + 4 <= n; j += 4) {
            int s0 = __shfl_sync(0xFFFFFFFFu, si, j);
            int s1 = __shfl_sync(0xFFFFFFFFu, si, j + 1);
            int s2 = __shfl_sync(0xFFFFFFFFu, si, j + 2);
            int s3 = __shfl_sync(0xFFFFFFFFu, si, j + 3);
            float m0 = __shfl_sync(0xFFFFFFFFu, ni, j);
            float m1 = __shfl_sync(0xFFFFFFFFu, ni, j + 1);
            float m2 = __shfl_sync(0xFFFFFFFFu, ni, j + 2);
            float m3 = __shfl_sync(0xFFFFFFFFu, ni, j + 3);
            float4 v0 = h[s0 * 32 + lane];
            float4 v1 = h[s1 * 32 + lane];
            float4 v2 = h[s2 * 32 + lane];
            float4 v3 = h[s3 * 32 + lane];
            acc.x += v0.x * m0; acc.y += v0.y * m0; acc.z += v0.z * m0; acc.w += v0.w * m0;
            acc.x += v1.x * m1; acc.y += v1.y * m1; acc.z += v1.z * m1; acc.w += v1.w * m1;
            acc.x += v2.x * m2; acc.y += v2.y * m2; acc.z += v2.z * m2; acc.w += v2.w * m2;
            acc.x += v3.x * m3; acc.y += v3.y * m3; acc.z += v3.z * m3; acc.w += v3.w * m3;
        }
        for (; j < n; j++) {
            int   s0 = __shfl_sync(0xFFFFFFFFu, si, j);
            float m0 = __shfl_sync(0xFFFFFFFFu, ni, j);
            float4 v0 = h[s0 * 32 + lane];
            acc.x += v0.x * m0; acc.y += v0.y * m0; acc.z += v0.z * m0; acc.w += v0.w * m0;
        }
    }
    float dn = g_norm[warp];
    acc.x *= dn; acc.y *= dn; acc.z *= dn; acc.w *= dn;
    reinterpret_cast<float4*>(g_agg)[warp * 32 + lane] = acc;
}

// ---------------------------------------------------------------------------
// Epilogue GEMM (unchanged from round 3): out = relu?(agg @ W + b)
// 128x128 tile, 512 threads, LDS.128 A, packed fma.rn.f32x2.
// ---------------------------------------------------------------------------
template <bool LAYER1>
__global__ __launch_bounds__(512) void epilogue_kernel(
    const float* __restrict__ W, const float* __restrict__ bias,
    float* __restrict__ outp) {
    extern __shared__ float smem[];
    float* sW = smem;           // [128][128]
    float* sH = smem + D * D;   // [128][128]

    int tid  = threadIdx.x;
    int row0 = blockIdx.x * 128;

    #pragma unroll 4
    for (int i = tid; i < D * D / 4; i += 512)
        reinterpret_cast<float4*>(sW)[i] =
            reinterpret_cast<const float4*>(W)[i];

    for (int i = tid; i < 128 * (D / 4); i += 512) {
        int r  = i >> 5;
        int c4 = i & 31;
        int node = row0 + r;
        float4 v = make_float4(0.f, 0.f, 0.f, 0.f);
        if (node < N_NODES)
            v = reinterpret_cast<const float4*>(g_agg)[node * 32 + c4];
        reinterpret_cast<float4*>(sH)[i] = v;
    }
    __syncthreads();

    int tx = tid & 31;
    int ty = tid >> 5;

    unsigned long long acc[8][2];
    #pragma unroll
    for (int r = 0; r < 8; r++) { acc[r][0] = 0ull; acc[r][1] = 0ull; }

    for (int k = 0; k < D; k += 4) {
        ulonglong2 b0 = reinterpret_cast<const ulonglong2*>(&sW[(k + 0) * D])[tx];
        ulonglong2 b1 = reinterpret_cast<const ulonglong2*>(&sW[(k + 1) * D])[tx];
        ulonglong2 b2 = reinterpret_cast<const ulonglong2*>(&sW[(k + 2) * D])[tx];
        ulonglong2 b3 = reinterpret_cast<const ulonglong2*>(&sW[(k + 3) * D])[tx];
        #pragma unroll
        for (int r = 0; r < 8; r++) {
            float4 a4 = *reinterpret_cast<const float4*>(
                &sH[(ty * 8 + r) * D + k]);
            unsigned long long a2;
            asm("mov.b64 %0, {%1, %1};" : "=l"(a2) : "f"(a4.x));
            asm("fma.rn.f32x2 %0, %1, %2, %0;" : "+l"(acc[r][0]) : "l"(a2), "l"(b0.x));
            asm("fma.rn.f32x2 %0, %1, %2, %0;" : "+l"(acc[r][1]) : "l"(a2), "l"(b0.y));
            asm("mov.b64 %0, {%1, %1};" : "=l"(a2) : "f"(a4.y));
            asm("fma.rn.f32x2 %0, %1, %2, %0;" : "+l"(acc[r][0]) : "l"(a2), "l"(b1.x));
            asm("fma.rn.f32x2 %0, %1, %2, %0;" : "+l"(acc[r][1]) : "l"(a2), "l"(b1.y));
            asm("mov.b64 %0, {%1, %1};" : "=l"(a2) : "f"(a4.z));
            asm("fma.rn.f32x2 %0, %1, %2, %0;" : "+l"(acc[r][0]) : "l"(a2), "l"(b2.x));
            asm("fma.rn.f32x2 %0, %1, %2, %0;" : "+l"(acc[r][1]) : "l"(a2), "l"(b2.y));
            asm("mov.b64 %0, {%1, %1};" : "=l"(a2) : "f"(a4.w));
            asm("fma.rn.f32x2 %0, %1, %2, %0;" : "+l"(acc[r][0]) : "l"(a2), "l"(b3.x));
            asm("fma.rn.f32x2 %0, %1, %2, %0;" : "+l"(acc[r][1]) : "l"(a2), "l"(b3.y));
        }
    }

    float4 bb = reinterpret_cast<const float4*>(bias)[tx];
    #pragma unroll
    for (int r = 0; r < 8; r++) {
        int node = row0 + ty * 8 + r;
        if (node < N_NODES) {
            float4 o;
            asm("mov.b64 {%0, %1}, %2;" : "=f"(o.x), "=f"(o.y) : "l"(acc[r][0]));
            asm("mov.b64 {%0, %1}, %2;" : "=f"(o.z), "=f"(o.w) : "l"(acc[r][1]));
            o.x += bb.x; o.y += bb.y; o.z += bb.z; o.w += bb.w;
            if (LAYER1) {
                o.x = fmaxf(o.x, 0.f); o.y = fmaxf(o.y, 0.f);
                o.z = fmaxf(o.z, 0.f); o.w = fmaxf(o.w, 0.f);
            }
            float* dst = LAYER1 ? g_h1 : outp;
            reinterpret_cast<float4*>(dst)[node * 32 + tx] = o;
        }
    }
}

// ---------------------------------------------------------------------------
// Launch
// ---------------------------------------------------------------------------
extern "C" void kernel_launch(void* const* d_in, const int* in_sizes, int n_in,
                              void* d_out, int out_size) {
    const float* features = (const float*)d_in[0];
    const int*   src      = (const int*)d_in[1];
    const int*   dst      = (const int*)d_in[2];
    const float* W0       = (const float*)d_in[3];
    const float* b0       = (const float*)d_in[4];
    const float* W1       = (const float*)d_in[5];
    const float* b1       = (const float*)d_in[6];
    float* out = (float*)d_out;

    const int SMEM_EPI = (D * D + 128 * D) * sizeof(float);  // 128 KB
    cudaFuncSetAttribute(epilogue_kernel<true>,
                         cudaFuncAttributeMaxDynamicSharedMemorySize, SMEM_EPI);
    cudaFuncSetAttribute(epilogue_kernel<false>,
                         cudaFuncAttributeMaxDynamicSharedMemorySize, SMEM_EPI);

    const int nodesBlocks = (N_NODES + 255) / 256;
    const int edgeBlocks  = (N_EDGES + 255) / 256;
    const int aggBlocks   = (N_NODES + 7) / 8;
    const int epiBlocks   = (N_NODES + 127) / 128;

    // CSR build
    zero_kernel<<<nodesBlocks, 256>>>();
    hist_kernel<<<edgeBlocks, 256>>>(dst);
    scanA_kernel<<<NB, SCAN_BLK>>>();
    scanB_kernel<<<1, 64>>>();
    scanC_kernel<<<NB, SCAN_BLK>>>();
    fill_kernel<<<edgeBlocks, 256>>>(src, dst);

    // Layer 1
    aggregate_kernel<true><<<aggBlocks, 256>>>((const float4*)features);
    epilogue_kernel<true><<<epiBlocks, 512, SMEM_EPI>>>(W0, b0, nullptr);

    // Layer 2
    aggregate_kernel<false><<<aggBlocks, 256>>>(nullptr);
    epilogue_kernel<false><<<epiBlocks, 512, SMEM_EPI>>>(W1, b1, out);
}